// round 13
// baseline (speedup 1.0000x reference)
#include <cuda_runtime.h>
#include <cuda_fp16.h>
#include <cstdint>

// ---------------- problem constants ----------------
#define D_   256
#define V_   8192
#define B_   64
#define T_   16
#define L_   1024          // B*T
#define C_   64            // C_STD
#define N_   1024          // T*C_STD
#define ZQ_SIZE  (B_*N_*D_)            // 16777216
#define OFF_LOSS (ZQ_SIZE)
#define OFF_IDX  (ZQ_SIZE+1)
#define NIDX     (L_*85)
#define OFF_CS   (OFF_IDX + NIDX)
#define MAXM     (L_*64)               // 65536

#define LO_SCALE 2048.0f
#define LO_INV   (1.0f/2048.0f)

typedef unsigned long long ull;

// ---------------- device scratch ----------------
__device__ float g_en[V_*D_];          // normalized embedding (8 MB)
__device__ __half g_enh[V_*512];       // fp16 split codes, per k-chunk [hi32|lo32], lo scaled 2048 (8 MB)
__device__ float g_Bt[D_*768];
__device__ float g_E[V_*768];          // phi conv of codes (24 MB)
__device__ float g_zl[L_*C_*D_];       // z_LND (64 MB)
__device__ float g_fhat[L_*C_*D_];     // running f_hat (64 MB)
__device__ __half g_qh[MAXM*512];      // fp16 split queries (64 MB)
__device__ ull   g_keys[MAXM];
__device__ int   g_idxcur[MAXM];
__device__ float g_counts[V_];
__device__ double g_loss;

// ---------------- helpers ----------------
__device__ __forceinline__ float blockReduceSum(float v) {
    __shared__ float sh[8];
    int lane = threadIdx.x & 31, w = threadIdx.x >> 5;
    #pragma unroll
    for (int o = 16; o; o >>= 1) v += __shfl_down_sync(0xffffffffu, v, o);
    if (lane == 0) sh[w] = v;
    __syncthreads();
    if (w == 0) {
        v = (lane < 8) ? sh[lane] : 0.f;
        #pragma unroll
        for (int o = 4; o; o >>= 1) v += __shfl_down_sync(0xffffffffu, v, o);
        if (lane == 0) sh[0] = v;
    }
    __syncthreads();
    return sh[0];
}

__device__ __forceinline__ unsigned order_f(float f) {
    unsigned u = __float_as_uint(f);
    return (u & 0x80000000u) ? ~u : (u | 0x80000000u);
}

__device__ __forceinline__ uint32_t smem_u32(const void* p) {
    uint32_t a;
    asm("{ .reg .u64 t; cvta.to.shared.u64 t, %1; cvt.u32.u64 %0, t; }" : "=r"(a) : "l"(p));
    return a;
}

__device__ __forceinline__ void cp16(uint32_t saddr, const void* g) {
    asm volatile("cp.async.cg.shared.global [%0], [%1], 16;" :: "r"(saddr), "l"(g) : "memory");
}
#define CP_COMMIT() asm volatile("cp.async.commit_group;" ::: "memory")

__device__ __forceinline__ void mma16(float* d, const uint32_t* a, const uint32_t* b) {
    asm("mma.sync.aligned.m16n8k16.row.col.f32.f16.f16.f32 "
        "{%0,%1,%2,%3}, {%4,%5,%6,%7}, {%8,%9}, {%0,%1,%2,%3};"
        : "+f"(d[0]), "+f"(d[1]), "+f"(d[2]), "+f"(d[3])
        : "r"(a[0]), "r"(a[1]), "r"(a[2]), "r"(a[3]), "r"(b[0]), "r"(b[1]));
}

__device__ __forceinline__ void ldsm4(uint32_t* r, uint32_t addr) {
    asm volatile("ldmatrix.sync.aligned.m8n8.x4.shared.b16 {%0,%1,%2,%3}, [%4];"
        : "=r"(r[0]), "=r"(r[1]), "=r"(r[2]), "=r"(r[3]) : "r"(addr));
}

// fp16 split with scaled low word: x ~= hi + lo/2048, lo stays fp16-normal
__device__ __forceinline__ void hsplit(float x, __half& hi, __half& lo) {
    hi = __float2half_rn(x);
    lo = __float2half_rn((x - __half2float(hi)) * LO_SCALE);
}

// ---------------- prep kernels ----------------
__global__ void k_norm_embed(const float* __restrict__ emb) {
    int v = blockIdx.x, d = threadIdx.x;
    float x = emb[v*D_ + d];
    float ss = blockReduceSum(x*x);
    float inv = 1.0f / fmaxf(sqrtf(ss), 1e-12f);
    float e = x * inv;
    g_en[v*D_ + d] = e;
    __half hi, lo;
    hsplit(e, hi, lo);
    int kt = d >> 5, pos = d & 31;
    g_enh[v*512 + kt*64 + pos] = hi;
    g_enh[v*512 + kt*64 + 32 + pos] = lo;
    if (d == 0) g_counts[v] = 0.f;
    if (v == 0 && d == 0) g_loss = 0.0;
}

__global__ void k_scatter_z(const float* __restrict__ z, const int* __restrict__ chans) {
    int row = blockIdx.x;
    int d = threadIdx.x;
    int b = row >> 10, n = row & 1023;
    float x = z[row*D_ + d];
    float ss = blockReduceSum(x*x);
    float inv = 1.0f / fmaxf(sqrtf(ss), 1e-12f);
    int csrc = n & 63, t = n >> 6;
    int ch = chans[b*N_ + csrc];
    int l = (b << 4) + t;
    int off = ((l << 6) + ch)*D_ + d;
    g_zl[off] = x * inv;
    g_fhat[off] = 0.f;
}

__global__ void k_transpose_w(const float* __restrict__ w) {
    int e = blockIdx.x * 256 + threadIdx.x;
    int o = e / 768, rem = e % 768;
    int i = rem / 3, k = rem % 3;
    g_Bt[i*768 + o*3 + k] = w[e];
}

// E = en(8192x256) @ Bt(256x768)
__global__ __launch_bounds__(256) void k_gemm_E() {
    __shared__ float As[32][68];
    __shared__ float Bs[32][68];
    int tid = threadIdx.x, tx = tid & 15, ty = tid >> 4;
    int rb = blockIdx.x * 64, cb = blockIdx.y * 64;
    float acc[4][4];
    #pragma unroll
    for (int i = 0; i < 4; i++)
        #pragma unroll
        for (int j = 0; j < 4; j++) acc[i][j] = 0.f;
    for (int kt = 0; kt < D_/32; kt++) {
        #pragma unroll
        for (int i = 0; i < 2; i++) {
            int f4 = tid + i*256;
            int r = f4 >> 3, kq = (f4 & 7) * 4;
            float4 v = *(const float4*)&g_en[(rb + r)*D_ + kt*32 + kq];
            As[kq+0][r] = v.x; As[kq+1][r] = v.y; As[kq+2][r] = v.z; As[kq+3][r] = v.w;
        }
        #pragma unroll
        for (int i = 0; i < 2; i++) {
            int f4 = tid + i*256;
            int r = f4 >> 4, cq = (f4 & 15) * 4;
            float4 v = *(const float4*)&g_Bt[(kt*32 + r)*768 + cb + cq];
            *(float4*)&Bs[r][cq] = v;
        }
        __syncthreads();
        #pragma unroll
        for (int kk = 0; kk < 32; kk++) {
            float4 a = *(const float4*)&As[kk][ty*4];
            float4 b = *(const float4*)&Bs[kk][tx*4];
            float ar[4] = {a.x, a.y, a.z, a.w};
            float br[4] = {b.x, b.y, b.z, b.w};
            #pragma unroll
            for (int i = 0; i < 4; i++)
                #pragma unroll
                for (int j = 0; j < 4; j++) acc[i][j] += ar[i] * br[j];
        }
        __syncthreads();
    }
    #pragma unroll
    for (int i = 0; i < 4; i++)
        #pragma unroll
        for (int j = 0; j < 4; j++)
            g_E[(rb + ty*4 + i)*768 + cb + tx*4 + j] = acc[i][j];
}

// block means of residual, L2-normalized, fp16-split (lo scaled)
__global__ void k_meansQ(int g) {
    int row = blockIdx.x;
    int d = threadIdx.x;
    int l = row / g, j = row % g;
    int s = C_ / g;
    int base = (l*C_ + j*s)*D_ + d;
    float sum = 0.f;
    for (int c = 0; c < s; c++) sum += g_zl[base + c*D_] - g_fhat[base + c*D_];
    sum *= (1.0f / s);
    float ss = blockReduceSum(sum*sum);
    float inv = 1.0f / fmaxf(sqrtf(ss), 1e-12f);
    sum *= inv;
    __half hi, lo;
    hsplit(sum, hi, lo);
    int kt = d >> 5, pos = d & 31;
    g_qh[(size_t)row*512 + kt*64 + pos] = hi;
    g_qh[(size_t)row*512 + kt*64 + 32 + pos] = lo;
    if (d == 0) g_keys[row] = 0ULL;
}

// ---------------- scaled fp16-split mma.sync fused GEMM + argmax ----------------
// BM=64, BN=128/pass, BK=32; 256 thr, 8 warps (2M x 4N), warp tile 32x32.
// 2 CTAs/SM (96KB smem each) -> same 16 warps/SM but decoupled barriers.
// Stage = A tile (64x128B) + B tile (128x128B) = 24KB; 4 stages = 96KB.
#define NSTAGE  4
#define TILE_A  8192
#define TILE_BB 16384
#define STAGE_B (TILE_A + TILE_BB)
#define QSMEM   (NSTAGE*STAGE_B)   // 98304

__device__ __forceinline__ void q_load_stage(uint32_t sb, int slot,
        const __half* Abase, const __half* Bbase, int pass, int kt, int tid) {
    uint32_t stg = sb + (uint32_t)slot*STAGE_B;
    if (tid < 128) {                     // A: 64 rows, 2 threads/row, 4 cp16 each
        int r = tid >> 1, half = tid & 1;
        const char* g = (const char*)(Abase + (size_t)r*512) + kt*128;
        uint32_t rowb = stg + (uint32_t)r*128;
        #pragma unroll
        for (int j = 0; j < 4; j++) {
            int c = half*4 + j;
            cp16(rowb + (uint32_t)((c ^ (r & 7)) << 4), g + c*16);
        }
    } else {                             // B: 128 rows, 1 thread/row, 8 cp16 each
        int r = tid - 128;
        const char* g = (const char*)(Bbase + (size_t)(pass*128 + r)*512) + kt*128;
        uint32_t rowb = stg + TILE_A + (uint32_t)r*128;
        #pragma unroll
        for (int c = 0; c < 8; c++)
            cp16(rowb + (uint32_t)((c ^ (r & 7)) << 4), g + c*16);
    }
}

__global__ __launch_bounds__(256, 2) void k_qmma(int Vper) {
    extern __shared__ float smf[];
    uint32_t sb = smem_u32(smf);
    int tid = threadIdx.x;
    int lane = tid & 31, wid = tid >> 5;
    int quad = lane >> 2, tq = lane & 3;
    int mbase = (wid >> 2) * 32;         // warp_m in {0,1}
    int nbase = (wid & 3) * 32;          // warp_n in {0..3}
    int rowbase = blockIdx.x * 64;
    int ctaV = blockIdx.y * Vper;
    int npass = Vper >> 7;
    int niter = npass * 8;

    const __half* Abase = g_qh + (size_t)rowbase * 512;
    const __half* Bbase = g_enh + (size_t)ctaV * 512;

    // ldmatrix address components
    int l7 = lane & 7;
    int l16 = (lane >> 4) & 1;
    int bl3 = (lane >> 3) & 1;
    uint32_t aRow[2], bRow[2];
    #pragma unroll
    for (int mt = 0; mt < 2; mt++)
        aRow[mt] = (uint32_t)(mbase + mt*16 + (lane & 15)) * 128u;
    #pragma unroll
    for (int np = 0; np < 2; np++)
        bRow[np] = (uint32_t)(nbase + np*16 + l16*8 + l7) * 128u;

    float accH[2][4][4], accM[2][4][4];
    float bv[4]; int bi[4];
    #pragma unroll
    for (int i = 0; i < 4; i++) { bv[i] = -1e30f; bi[i] = 0; }

    // prologue: fill 3 stages (prefetch distance 3)
    q_load_stage(sb, 0, Abase, Bbase, 0, 0, tid); CP_COMMIT();
    q_load_stage(sb, 1, Abase, Bbase, 0, 1, tid); CP_COMMIT();
    q_load_stage(sb, 2, Abase, Bbase, 0, 2, tid); CP_COMMIT();

    int s = 0;
    for (int it = 0; it < niter; it++) {
        int pass = it >> 3, kt = it & 7;

        asm volatile("cp.async.wait_group 2;" ::: "memory");
        __syncthreads();

        int ld = it + 3;
        if (ld < niter) {
            int s2 = s + 3; if (s2 >= NSTAGE) s2 -= NSTAGE;
            q_load_stage(sb, s2, Abase, Bbase, ld >> 3, ld & 7, tid);
        }
        CP_COMMIT();

        if (kt == 0) {
            #pragma unroll
            for (int mt = 0; mt < 2; mt++)
                #pragma unroll
                for (int nt = 0; nt < 4; nt++)
                    #pragma unroll
                    for (int rg = 0; rg < 4; rg++) { accH[mt][nt][rg] = 0.f; accM[mt][nt][rg] = 0.f; }
        }

        uint32_t tA = sb + (uint32_t)s*STAGE_B;
        uint32_t tB = tA + TILE_A;
        #pragma unroll
        for (int kg = 0; kg < 2; kg++) {
            uint32_t ah[2][4], al[2][4];
            int chA = (kg << 1) + l16;
            #pragma unroll
            for (int mt = 0; mt < 2; mt++) {
                ldsm4(ah[mt], tA + aRow[mt] + (uint32_t)((chA ^ l7) << 4));
                ldsm4(al[mt], tA + aRow[mt] + (uint32_t)(((chA + 4) ^ l7) << 4));
            }
            int chB = (kg << 1) + bl3;
            #pragma unroll
            for (int np = 0; np < 2; np++) {
                uint32_t bh_[4], bl_[4];
                ldsm4(bh_, tB + bRow[np] + (uint32_t)((chB ^ l7) << 4));
                ldsm4(bl_, tB + bRow[np] + (uint32_t)(((chB + 4) ^ l7) << 4));
                #pragma unroll
                for (int h = 0; h < 2; h++) {
                    int nt = np*2 + h;
                    #pragma unroll
                    for (int mt = 0; mt < 2; mt++) {
                        mma16(accH[mt][nt], ah[mt], bh_ + h*2);
                        mma16(accM[mt][nt], al[mt], bh_ + h*2);
                        mma16(accM[mt][nt], ah[mt], bl_ + h*2);
                    }
                }
            }
        }

        if (kt == 7) {
            int vb = ctaV + pass*128 + nbase;
            #pragma unroll
            for (int mt = 0; mt < 2; mt++) {
                #pragma unroll
                for (int nt = 0; nt < 4; nt++) {
                    int c0 = vb + nt*8 + tq*2;
                    float v0 = accH[mt][nt][0] + accM[mt][nt][0]*LO_INV;
                    float v1 = accH[mt][nt][1] + accM[mt][nt][1]*LO_INV;
                    float v2 = accH[mt][nt][2] + accM[mt][nt][2]*LO_INV;
                    float v3 = accH[mt][nt][3] + accM[mt][nt][3]*LO_INV;
                    int slo = mt*2, shi = mt*2 + 1;
                    if (v0 > bv[slo]) { bv[slo] = v0; bi[slo] = c0; }
                    if (v1 > bv[slo]) { bv[slo] = v1; bi[slo] = c0 + 1; }
                    if (v2 > bv[shi]) { bv[shi] = v2; bi[shi] = c0; }
                    if (v3 > bv[shi]) { bv[shi] = v3; bi[shi] = c0 + 1; }
                }
            }
        }
        s++; if (s == NSTAGE) s = 0;
    }

    // reduce across the 4 lanes of each quad-group, then atomicMax per row
    #pragma unroll
    for (int slot = 0; slot < 4; slot++) {
        float v = bv[slot]; int i = bi[slot];
        #pragma unroll
        for (int off = 1; off < 4; off <<= 1) {
            float v2 = __shfl_xor_sync(0xffffffffu, v, off);
            int   i2 = __shfl_xor_sync(0xffffffffu, i, off);
            if (v2 > v || (v2 == v && i2 < i)) { v = v2; i = i2; }
        }
        if (tq == 0) {
            int mt = slot >> 1;
            int row = rowbase + mbase + mt*16 + quad + ((slot & 1) ? 8 : 0);
            ull key = ((ull)order_f(v) << 32) | (ull)(0xFFFFFFFFu - (unsigned)i);
            atomicMax(&g_keys[row], key);
        }
    }
}

__global__ void k_finalize(int g, int colbase, int M, float* __restrict__ out) {
    int row = blockIdx.x * 256 + threadIdx.x;
    if (row >= M) return;
    ull key = g_keys[row];
    int idx = (int)(0xFFFFFFFFu - (unsigned)(key & 0xFFFFFFFFu));
    g_idxcur[row] = idx;
    int l = row / g, j = row % g;
    out[OFF_IDX + l*85 + colbase + j] = (float)idx;
    atomicAdd(&g_counts[idx], 1.0f);
}

__global__ void k_assemble(int g, const float* __restrict__ phib) {
    int l = blockIdx.x, d = threadIdx.x;
    int s = C_ / g;
    __shared__ int sidx[64];
    if (d < g) sidx[d] = g_idxcur[l*g + d];
    __syncthreads();
    float bb = phib[d];
    float lsum = 0.f;
    for (int c = 0; c < C_; c++) {
        int vb = sidx[c / s];
        float y = g_E[vb*768 + d*3 + 1] + bb;
        if (c > 0)      y += g_E[sidx[(c-1)/s]*768 + d*3 + 0];
        if (c < C_-1)   y += g_E[sidx[(c+1)/s]*768 + d*3 + 2];
        float h = 0.5f*g_en[vb*D_ + d] + 0.5f*y;
        int off = (l*C_ + c)*D_ + d;
        float f = g_fhat[off] + h;
        g_fhat[off] = f;
        float diff = f - g_zl[off];
        lsum += diff * diff;
    }
    float tot = blockReduceSum(lsum);
    if (d == 0) atomicAdd(&g_loss, (double)tot);
}

__global__ void k_gather_zq(const int* __restrict__ chans, float* __restrict__ out) {
    int row = blockIdx.x;
    int d = threadIdx.x;
    int b = row >> 10, n = row & 1023;
    int csrc = n & 63, t = n >> 6;
    int ch = chans[b*N_ + csrc];
    int l = (b << 4) + t;
    out[row*D_ + d] = g_fhat[((l << 6) + ch)*D_ + d];
}

__global__ void k_tail(const float* __restrict__ cs, float* __restrict__ out) {
    int v = blockIdx.x * 256 + threadIdx.x;
    out[OFF_CS + v] = 0.99f * cs[v] + 0.01f * g_counts[v];
    if (v == 0)
        out[OFF_LOSS] = (float)(g_loss * (1.25 / (4.0 * (double)(L_*C_*D_))));
}

// ---------------- launch ----------------
extern "C" void kernel_launch(void* const* d_in, const int* in_sizes, int n_in,
                              void* d_out, int out_size) {
    const float* z     = (const float*)d_in[0];
    const int*   chans = (const int*)d_in[1];
    const float* emb   = (const float*)d_in[3];
    const float* w     = (const float*)d_in[4];
    const float* phib  = (const float*)d_in[5];
    const float* cs    = (const float*)d_in[6];
    float* out = (float*)d_out;

    cudaFuncSetAttribute(k_qmma, cudaFuncAttributeMaxDynamicSharedMemorySize, QSMEM);

    const int gs[4]      = {1, 4, 16, 64};
    const int colbase[4] = {0, 1, 5, 21};
    // CTA counts (BM=64): 256 / 256 / 256 / 2048 -> 1 wave or ~7 even waves
    const int vsplit[4]  = {16, 4, 1, 2};

    // Launch order puts the first k_qmma at launch #4 (ncu capture slot).
    k_norm_embed<<<V_, 256>>>(emb);                            // #1
    k_scatter_z<<<B_*N_, 256>>>(z, chans);                     // #2
    k_meansQ<<<L_, 256>>>(1);                                  // #3
    k_qmma<<<dim3(L_/64, vsplit[0]), 256, QSMEM>>>(V_/vsplit[0]); // #4
    k_transpose_w<<<768, 256>>>(w);                            // #5
    k_gemm_E<<<dim3(V_/64, 12), 256>>>();                      // #6
    k_finalize<<<(L_ + 255)/256, 256>>>(1, colbase[0], L_, out);
    k_assemble<<<L_, 256>>>(1, phib);

    for (int r = 1; r < 4; r++) {
        int g = gs[r];
        int M = L_ * g;
        k_meansQ<<<M, 256>>>(g);
        k_qmma<<<dim3(M/64, vsplit[r]), 256, QSMEM>>>(V_ / vsplit[r]);
        k_finalize<<<(M + 255)/256, 256>>>(g, colbase[r], M, out);
        k_assemble<<<L_, 256>>>(g, phib);
    }

    k_gather_zq<<<B_*N_, 256>>>(chans, out);
    k_tail<<<V_/256, 256>>>(cs, out);
}

// round 14
// speedup vs baseline: 1.2372x; 1.2372x over previous
#include <cuda_runtime.h>
#include <cuda_fp16.h>
#include <cstdint>

// ---------------- problem constants ----------------
#define D_   256
#define V_   8192
#define B_   64
#define T_   16
#define L_   1024          // B*T
#define C_   64            // C_STD
#define N_   1024          // T*C_STD
#define ZQ_SIZE  (B_*N_*D_)            // 16777216
#define OFF_LOSS (ZQ_SIZE)
#define OFF_IDX  (ZQ_SIZE+1)
#define NIDX     (L_*85)
#define OFF_CS   (OFF_IDX + NIDX)
#define MAXM     (L_*64)               // 65536

#define LO_SCALE 2048.0f
#define LO_INV   (1.0f/2048.0f)

typedef unsigned long long ull;

// ---------------- device scratch ----------------
__device__ float g_en[V_*D_];          // normalized embedding (8 MB)
__device__ __half g_enh[V_*512];       // fp16 split codes, per k-chunk [hi32|lo32], lo scaled 2048 (8 MB)
__device__ float g_Bt[D_*768];
__device__ float g_E[V_*768];          // phi conv of codes (24 MB)
__device__ float g_zl[L_*C_*D_];       // z_LND (64 MB)
__device__ float g_fhat[L_*C_*D_];     // running f_hat (64 MB)
__device__ __half g_qh[MAXM*512];      // fp16 split queries (64 MB)
__device__ ull   g_keys[MAXM];
__device__ int   g_idxcur[MAXM];
__device__ float g_counts[V_];
__device__ double g_loss;

// ---------------- helpers ----------------
__device__ __forceinline__ float blockReduceSum(float v) {
    __shared__ float sh[8];
    int lane = threadIdx.x & 31, w = threadIdx.x >> 5;
    #pragma unroll
    for (int o = 16; o; o >>= 1) v += __shfl_down_sync(0xffffffffu, v, o);
    if (lane == 0) sh[w] = v;
    __syncthreads();
    if (w == 0) {
        v = (lane < 8) ? sh[lane] : 0.f;
        #pragma unroll
        for (int o = 4; o; o >>= 1) v += __shfl_down_sync(0xffffffffu, v, o);
        if (lane == 0) sh[0] = v;
    }
    __syncthreads();
    return sh[0];
}

__device__ __forceinline__ unsigned order_f(float f) {
    unsigned u = __float_as_uint(f);
    return (u & 0x80000000u) ? ~u : (u | 0x80000000u);
}

__device__ __forceinline__ uint32_t smem_u32(const void* p) {
    uint32_t a;
    asm("{ .reg .u64 t; cvta.to.shared.u64 t, %1; cvt.u32.u64 %0, t; }" : "=r"(a) : "l"(p));
    return a;
}

__device__ __forceinline__ void cp16(uint32_t saddr, const void* g) {
    asm volatile("cp.async.cg.shared.global [%0], [%1], 16;" :: "r"(saddr), "l"(g) : "memory");
}
#define CP_COMMIT() asm volatile("cp.async.commit_group;" ::: "memory")

__device__ __forceinline__ void mma16(float* d, const uint32_t* a, const uint32_t* b) {
    asm("mma.sync.aligned.m16n8k16.row.col.f32.f16.f16.f32 "
        "{%0,%1,%2,%3}, {%4,%5,%6,%7}, {%8,%9}, {%0,%1,%2,%3};"
        : "+f"(d[0]), "+f"(d[1]), "+f"(d[2]), "+f"(d[3])
        : "r"(a[0]), "r"(a[1]), "r"(a[2]), "r"(a[3]), "r"(b[0]), "r"(b[1]));
}

__device__ __forceinline__ void ldsm4(uint32_t* r, uint32_t addr) {
    asm volatile("ldmatrix.sync.aligned.m8n8.x4.shared.b16 {%0,%1,%2,%3}, [%4];"
        : "=r"(r[0]), "=r"(r[1]), "=r"(r[2]), "=r"(r[3]) : "r"(addr));
}

// fp16 split with scaled low word: x ~= hi + lo/2048, lo stays fp16-normal
__device__ __forceinline__ void hsplit(float x, __half& hi, __half& lo) {
    hi = __float2half_rn(x);
    lo = __float2half_rn((x - __half2float(hi)) * LO_SCALE);
}

// ---------------- prep kernels ----------------
__global__ void k_norm_embed(const float* __restrict__ emb) {
    int v = blockIdx.x, d = threadIdx.x;
    float x = emb[v*D_ + d];
    float ss = blockReduceSum(x*x);
    float inv = 1.0f / fmaxf(sqrtf(ss), 1e-12f);
    float e = x * inv;
    g_en[v*D_ + d] = e;
    __half hi, lo;
    hsplit(e, hi, lo);
    int kt = d >> 5, pos = d & 31;
    g_enh[v*512 + kt*64 + pos] = hi;
    g_enh[v*512 + kt*64 + 32 + pos] = lo;
    if (d == 0) g_counts[v] = 0.f;
    if (v == 0 && d == 0) g_loss = 0.0;
}

__global__ void k_scatter_z(const float* __restrict__ z, const int* __restrict__ chans) {
    int row = blockIdx.x;
    int d = threadIdx.x;
    int b = row >> 10, n = row & 1023;
    float x = z[row*D_ + d];
    float ss = blockReduceSum(x*x);
    float inv = 1.0f / fmaxf(sqrtf(ss), 1e-12f);
    int csrc = n & 63, t = n >> 6;
    int ch = chans[b*N_ + csrc];
    int l = (b << 4) + t;
    int off = ((l << 6) + ch)*D_ + d;
    g_zl[off] = x * inv;
    g_fhat[off] = 0.f;
}

__global__ void k_transpose_w(const float* __restrict__ w) {
    int e = blockIdx.x * 256 + threadIdx.x;
    int o = e / 768, rem = e % 768;
    int i = rem / 3, k = rem % 3;
    g_Bt[i*768 + o*3 + k] = w[e];
}

// E = en(8192x256) @ Bt(256x768)
__global__ __launch_bounds__(256) void k_gemm_E() {
    __shared__ float As[32][68];
    __shared__ float Bs[32][68];
    int tid = threadIdx.x, tx = tid & 15, ty = tid >> 4;
    int rb = blockIdx.x * 64, cb = blockIdx.y * 64;
    float acc[4][4];
    #pragma unroll
    for (int i = 0; i < 4; i++)
        #pragma unroll
        for (int j = 0; j < 4; j++) acc[i][j] = 0.f;
    for (int kt = 0; kt < D_/32; kt++) {
        #pragma unroll
        for (int i = 0; i < 2; i++) {
            int f4 = tid + i*256;
            int r = f4 >> 3, kq = (f4 & 7) * 4;
            float4 v = *(const float4*)&g_en[(rb + r)*D_ + kt*32 + kq];
            As[kq+0][r] = v.x; As[kq+1][r] = v.y; As[kq+2][r] = v.z; As[kq+3][r] = v.w;
        }
        #pragma unroll
        for (int i = 0; i < 2; i++) {
            int f4 = tid + i*256;
            int r = f4 >> 4, cq = (f4 & 15) * 4;
            float4 v = *(const float4*)&g_Bt[(kt*32 + r)*768 + cb + cq];
            *(float4*)&Bs[r][cq] = v;
        }
        __syncthreads();
        #pragma unroll
        for (int kk = 0; kk < 32; kk++) {
            float4 a = *(const float4*)&As[kk][ty*4];
            float4 b = *(const float4*)&Bs[kk][tx*4];
            float ar[4] = {a.x, a.y, a.z, a.w};
            float br[4] = {b.x, b.y, b.z, b.w};
            #pragma unroll
            for (int i = 0; i < 4; i++)
                #pragma unroll
                for (int j = 0; j < 4; j++) acc[i][j] += ar[i] * br[j];
        }
        __syncthreads();
    }
    #pragma unroll
    for (int i = 0; i < 4; i++)
        #pragma unroll
        for (int j = 0; j < 4; j++)
            g_E[(rb + ty*4 + i)*768 + cb + tx*4 + j] = acc[i][j];
}

// block means of residual, L2-normalized, fp16-split (lo scaled)
__global__ void k_meansQ(int g) {
    int row = blockIdx.x;
    int d = threadIdx.x;
    int l = row / g, j = row % g;
    int s = C_ / g;
    int base = (l*C_ + j*s)*D_ + d;
    float sum = 0.f;
    for (int c = 0; c < s; c++) sum += g_zl[base + c*D_] - g_fhat[base + c*D_];
    sum *= (1.0f / s);
    float ss = blockReduceSum(sum*sum);
    float inv = 1.0f / fmaxf(sqrtf(ss), 1e-12f);
    sum *= inv;
    __half hi, lo;
    hsplit(sum, hi, lo);
    int kt = d >> 5, pos = d & 31;
    g_qh[(size_t)row*512 + kt*64 + pos] = hi;
    g_qh[(size_t)row*512 + kt*64 + 32 + pos] = lo;
    if (d == 0) g_keys[row] = 0ULL;
}

// ---------------- scaled fp16-split mma.sync fused GEMM + argmax ----------------
// BM=128, BN=128/pass, BK=32; 512 thr, 16 warps (4M x 4N), warp tile 32x32.
// Two fp32 accumulators: accH (hi*hi) and accM (lo'*hi + hi*lo', scale 2048).
// Smem stage = A tile + B tile (each 128 rows x 128B [hi32|lo32]) = 32KB; 4 stages.
#define NSTAGE  4
#define TILE_B  16384
#define STAGE_B (2*TILE_B)
#define QSMEM   (NSTAGE*STAGE_B)   // 131072

__device__ __forceinline__ void q_load_stage(uint32_t sb, int slot,
        const __half* Abase, const __half* Bbase, int pass, int kt, int tid) {
    int tile = tid >> 8;                 // 0=A, 1=B  (256 threads each)
    int idx = tid & 255;
    int r = idx >> 1, half = idx & 1;    // 2 threads per 128B row
    const char* g = (tile == 0)
        ? (const char*)(Abase + (size_t)r*512) + kt*128
        : (const char*)(Bbase + (size_t)(pass*128 + r)*512) + kt*128;
    uint32_t rowb = sb + (uint32_t)slot*STAGE_B + (uint32_t)tile*TILE_B + (uint32_t)r*128;
    #pragma unroll
    for (int j = 0; j < 4; j++) {
        int c = half*4 + j;
        cp16(rowb + (uint32_t)((c ^ (r & 7)) << 4), g + c*16);
    }
}

__global__ __launch_bounds__(512, 1) void k_qmma(int Vper) {
    extern __shared__ float smf[];
    uint32_t sb = smem_u32(smf);
    int tid = threadIdx.x;
    int lane = tid & 31, wid = tid >> 5;
    int quad = lane >> 2, tq = lane & 3;
    int mbase = (wid >> 2) * 32;         // warp_m in {0..3}
    int nbase = (wid & 3) * 32;          // warp_n in {0..3}
    int rowbase = blockIdx.x * 128;
    int ctaV = blockIdx.y * Vper;
    int npass = Vper >> 7;
    int niter = npass * 8;

    const __half* Abase = g_qh + (size_t)rowbase * 512;
    const __half* Bbase = g_enh + (size_t)ctaV * 512;

    // ldmatrix address components
    int l7 = lane & 7;
    int l16 = (lane >> 4) & 1;
    int bl3 = (lane >> 3) & 1;
    uint32_t aRow[2], bRow[2];
    #pragma unroll
    for (int mt = 0; mt < 2; mt++)
        aRow[mt] = (uint32_t)(mbase + mt*16 + (lane & 15)) * 128u;
    #pragma unroll
    for (int np = 0; np < 2; np++)
        bRow[np] = (uint32_t)(nbase + np*16 + l16*8 + l7) * 128u;

    float accH[2][4][4], accM[2][4][4];
    float bv[4]; int bi[4];
    #pragma unroll
    for (int i = 0; i < 4; i++) { bv[i] = -1e30f; bi[i] = 0; }

    // prologue: fill 3 stages (prefetch distance 3)
    q_load_stage(sb, 0, Abase, Bbase, 0, 0, tid); CP_COMMIT();
    q_load_stage(sb, 1, Abase, Bbase, 0, 1, tid); CP_COMMIT();
    q_load_stage(sb, 2, Abase, Bbase, 0, 2, tid); CP_COMMIT();

    int s = 0;
    for (int it = 0; it < niter; it++) {
        int pass = it >> 3, kt = it & 7;

        asm volatile("cp.async.wait_group 2;" ::: "memory");
        __syncthreads();

        int ld = it + 3;
        if (ld < niter) {
            int s2 = s + 3; if (s2 >= NSTAGE) s2 -= NSTAGE;
            q_load_stage(sb, s2, Abase, Bbase, ld >> 3, ld & 7, tid);
        }
        CP_COMMIT();

        if (kt == 0) {
            #pragma unroll
            for (int mt = 0; mt < 2; mt++)
                #pragma unroll
                for (int nt = 0; nt < 4; nt++)
                    #pragma unroll
                    for (int rg = 0; rg < 4; rg++) { accH[mt][nt][rg] = 0.f; accM[mt][nt][rg] = 0.f; }
        }

        uint32_t tA = sb + (uint32_t)s*STAGE_B;
        uint32_t tB = tA + TILE_B;
        #pragma unroll
        for (int kg = 0; kg < 2; kg++) {
            uint32_t ah[2][4], al[2][4];
            int chA = (kg << 1) + l16;
            #pragma unroll
            for (int mt = 0; mt < 2; mt++) {
                ldsm4(ah[mt], tA + aRow[mt] + (uint32_t)((chA ^ l7) << 4));
                ldsm4(al[mt], tA + aRow[mt] + (uint32_t)(((chA + 4) ^ l7) << 4));
            }
            int chB = (kg << 1) + bl3;
            #pragma unroll
            for (int np = 0; np < 2; np++) {
                uint32_t bh_[4], bl_[4];
                ldsm4(bh_, tB + bRow[np] + (uint32_t)((chB ^ l7) << 4));
                ldsm4(bl_, tB + bRow[np] + (uint32_t)(((chB + 4) ^ l7) << 4));
                #pragma unroll
                for (int h = 0; h < 2; h++) {
                    int nt = np*2 + h;
                    #pragma unroll
                    for (int mt = 0; mt < 2; mt++) {
                        mma16(accH[mt][nt], ah[mt], bh_ + h*2);
                        mma16(accM[mt][nt], al[mt], bh_ + h*2);
                        mma16(accM[mt][nt], ah[mt], bl_ + h*2);
                    }
                }
            }
        }

        if (kt == 7) {
            int vb = ctaV + pass*128 + nbase;
            #pragma unroll
            for (int mt = 0; mt < 2; mt++) {
                #pragma unroll
                for (int nt = 0; nt < 4; nt++) {
                    int c0 = vb + nt*8 + tq*2;
                    float v0 = accH[mt][nt][0] + accM[mt][nt][0]*LO_INV;
                    float v1 = accH[mt][nt][1] + accM[mt][nt][1]*LO_INV;
                    float v2 = accH[mt][nt][2] + accM[mt][nt][2]*LO_INV;
                    float v3 = accH[mt][nt][3] + accM[mt][nt][3]*LO_INV;
                    int slo = mt*2, shi = mt*2 + 1;
                    if (v0 > bv[slo]) { bv[slo] = v0; bi[slo] = c0; }
                    if (v1 > bv[slo]) { bv[slo] = v1; bi[slo] = c0 + 1; }
                    if (v2 > bv[shi]) { bv[shi] = v2; bi[shi] = c0; }
                    if (v3 > bv[shi]) { bv[shi] = v3; bi[shi] = c0 + 1; }
                }
            }
        }
        s++; if (s == NSTAGE) s = 0;
    }

    // reduce across the 4 lanes of each quad-group, then atomicMax per row
    #pragma unroll
    for (int slot = 0; slot < 4; slot++) {
        float v = bv[slot]; int i = bi[slot];
        #pragma unroll
        for (int off = 1; off < 4; off <<= 1) {
            float v2 = __shfl_xor_sync(0xffffffffu, v, off);
            int   i2 = __shfl_xor_sync(0xffffffffu, i, off);
            if (v2 > v || (v2 == v && i2 < i)) { v = v2; i = i2; }
        }
        if (tq == 0) {
            int mt = slot >> 1;
            int row = rowbase + mbase + mt*16 + quad + ((slot & 1) ? 8 : 0);
            ull key = ((ull)order_f(v) << 32) | (ull)(0xFFFFFFFFu - (unsigned)i);
            atomicMax(&g_keys[row], key);
        }
    }
}

__global__ void k_finalize(int g, int colbase, int M, float* __restrict__ out) {
    int row = blockIdx.x * 256 + threadIdx.x;
    if (row >= M) return;
    ull key = g_keys[row];
    int idx = (int)(0xFFFFFFFFu - (unsigned)(key & 0xFFFFFFFFu));
    g_idxcur[row] = idx;
    int l = row / g, j = row % g;
    out[OFF_IDX + l*85 + colbase + j] = (float)idx;
    atomicAdd(&g_counts[idx], 1.0f);
}

__global__ void k_assemble(int g, const float* __restrict__ phib) {
    int l = blockIdx.x, d = threadIdx.x;
    int s = C_ / g;
    __shared__ int sidx[64];
    if (d < g) sidx[d] = g_idxcur[l*g + d];
    __syncthreads();
    float bb = phib[d];
    float lsum = 0.f;
    for (int c = 0; c < C_; c++) {
        int vb = sidx[c / s];
        float y = g_E[vb*768 + d*3 + 1] + bb;
        if (c > 0)      y += g_E[sidx[(c-1)/s]*768 + d*3 + 0];
        if (c < C_-1)   y += g_E[sidx[(c+1)/s]*768 + d*3 + 2];
        float h = 0.5f*g_en[vb*D_ + d] + 0.5f*y;
        int off = (l*C_ + c)*D_ + d;
        float f = g_fhat[off] + h;
        g_fhat[off] = f;
        float diff = f - g_zl[off];
        lsum += diff * diff;
    }
    float tot = blockReduceSum(lsum);
    if (d == 0) atomicAdd(&g_loss, (double)tot);
}

__global__ void k_gather_zq(const int* __restrict__ chans, float* __restrict__ out) {
    int row = blockIdx.x;
    int d = threadIdx.x;
    int b = row >> 10, n = row & 1023;
    int csrc = n & 63, t = n >> 6;
    int ch = chans[b*N_ + csrc];
    int l = (b << 4) + t;
    out[row*D_ + d] = g_fhat[((l << 6) + ch)*D_ + d];
}

__global__ void k_tail(const float* __restrict__ cs, float* __restrict__ out) {
    int v = blockIdx.x * 256 + threadIdx.x;
    out[OFF_CS + v] = 0.99f * cs[v] + 0.01f * g_counts[v];
    if (v == 0)
        out[OFF_LOSS] = (float)(g_loss * (1.25 / (4.0 * (double)(L_*C_*D_))));
}

// ---------------- launch ----------------
extern "C" void kernel_launch(void* const* d_in, const int* in_sizes, int n_in,
                              void* d_out, int out_size) {
    const float* z     = (const float*)d_in[0];
    const int*   chans = (const int*)d_in[1];
    const float* emb   = (const float*)d_in[3];
    const float* w     = (const float*)d_in[4];
    const float* phib  = (const float*)d_in[5];
    const float* cs    = (const float*)d_in[6];
    float* out = (float*)d_out;

    cudaFuncSetAttribute(k_qmma, cudaFuncAttributeMaxDynamicSharedMemorySize, QSMEM);

    const int gs[4]      = {1, 4, 16, 64};
    const int colbase[4] = {0, 1, 5, 21};
    // CTA counts (BM=128): 256 / 256 / 128 / 1024 -> round 4 runs ~7 even waves
    const int vsplit[4]  = {16, 4, 1, 2};

    // Launch order puts the first k_qmma at launch #4 (ncu capture slot).
    k_norm_embed<<<V_, 256>>>(emb);                            // #1
    k_scatter_z<<<B_*N_, 256>>>(z, chans);                     // #2
    k_meansQ<<<L_, 256>>>(1);                                  // #3
    k_qmma<<<dim3(L_/128, vsplit[0]), 512, QSMEM>>>(V_/vsplit[0]); // #4
    k_transpose_w<<<768, 256>>>(w);                            // #5
    k_gemm_E<<<dim3(V_/64, 12), 256>>>();                      // #6
    k_finalize<<<(L_ + 255)/256, 256>>>(1, colbase[0], L_, out);
    k_assemble<<<L_, 256>>>(1, phib);

    for (int r = 1; r < 4; r++) {
        int g = gs[r];
        int M = L_ * g;
        k_meansQ<<<M, 256>>>(g);
        k_qmma<<<dim3(M/128, vsplit[r]), 512, QSMEM>>>(V_ / vsplit[r]);
        k_finalize<<<(M + 255)/256, 256>>>(g, colbase[r], M, out);
        k_assemble<<<L_, 256>>>(g, phib);
    }

    k_gather_zq<<<B_*N_, 256>>>(chans, out);
    k_tail<<<V_/256, 256>>>(cs, out);
}

// round 16
// speedup vs baseline: 1.2970x; 1.0483x over previous
#include <cuda_runtime.h>
#include <cuda_fp16.h>
#include <cstdint>

// ---------------- problem constants ----------------
#define D_   256
#define V_   8192
#define B_   64
#define T_   16
#define L_   1024          // B*T
#define C_   64            // C_STD
#define N_   1024          // T*C_STD
#define ZQ_SIZE  (B_*N_*D_)            // 16777216
#define OFF_LOSS (ZQ_SIZE)
#define OFF_IDX  (ZQ_SIZE+1)
#define NIDX     (L_*85)
#define OFF_CS   (OFF_IDX + NIDX)
#define MAXM     (L_*64)               // 65536

#define LO_SCALE 2048.0f
#define LO_INV   (1.0f/2048.0f)

typedef unsigned long long ull;

// ---------------- device scratch ----------------
__device__ float g_en[V_*D_];          // normalized embedding (8 MB)
__device__ __half g_enh[V_*512];       // fp16 split codes, per k-chunk [hi32|lo32], lo scaled 2048 (8 MB)
__device__ float g_Bt[D_*768];
__device__ float g_E[V_*768];          // phi conv of codes (24 MB)
__device__ float g_zl[L_*C_*D_];       // z_LND (64 MB)
__device__ float g_fhat[L_*C_*D_];     // running f_hat (64 MB)
__device__ __half g_qh[MAXM*512];      // fp16 split queries (64 MB)
__device__ ull   g_keys[MAXM];
__device__ float g_counts[V_];
__device__ double g_loss;

// ---------------- helpers ----------------
__device__ __forceinline__ float blockReduceSum(float v) {
    __shared__ float sh[8];
    int lane = threadIdx.x & 31, w = threadIdx.x >> 5;
    #pragma unroll
    for (int o = 16; o; o >>= 1) v += __shfl_down_sync(0xffffffffu, v, o);
    if (lane == 0) sh[w] = v;
    __syncthreads();
    if (w == 0) {
        v = (lane < 8) ? sh[lane] : 0.f;
        #pragma unroll
        for (int o = 4; o; o >>= 1) v += __shfl_down_sync(0xffffffffu, v, o);
        if (lane == 0) sh[0] = v;
    }
    __syncthreads();
    return sh[0];
}

__device__ __forceinline__ unsigned order_f(float f) {
    unsigned u = __float_as_uint(f);
    return (u & 0x80000000u) ? ~u : (u | 0x80000000u);
}

__device__ __forceinline__ uint32_t smem_u32(const void* p) {
    uint32_t a;
    asm("{ .reg .u64 t; cvta.to.shared.u64 t, %1; cvt.u32.u64 %0, t; }" : "=r"(a) : "l"(p));
    return a;
}

__device__ __forceinline__ void cp16(uint32_t saddr, const void* g) {
    asm volatile("cp.async.cg.shared.global [%0], [%1], 16;" :: "r"(saddr), "l"(g) : "memory");
}
#define CP_COMMIT() asm volatile("cp.async.commit_group;" ::: "memory")

__device__ __forceinline__ void mma16(float* d, const uint32_t* a, const uint32_t* b) {
    asm("mma.sync.aligned.m16n8k16.row.col.f32.f16.f16.f32 "
        "{%0,%1,%2,%3}, {%4,%5,%6,%7}, {%8,%9}, {%0,%1,%2,%3};"
        : "+f"(d[0]), "+f"(d[1]), "+f"(d[2]), "+f"(d[3])
        : "r"(a[0]), "r"(a[1]), "r"(a[2]), "r"(a[3]), "r"(b[0]), "r"(b[1]));
}

__device__ __forceinline__ void ldsm4(uint32_t* r, uint32_t addr) {
    asm volatile("ldmatrix.sync.aligned.m8n8.x4.shared.b16 {%0,%1,%2,%3}, [%4];"
        : "=r"(r[0]), "=r"(r[1]), "=r"(r[2]), "=r"(r[3]) : "r"(addr));
}

// fp16 split with scaled low word: x ~= hi + lo/2048, lo stays fp16-normal
__device__ __forceinline__ void hsplit(float x, __half& hi, __half& lo) {
    hi = __float2half_rn(x);
    lo = __float2half_rn((x - __half2float(hi)) * LO_SCALE);
}

// ---------------- prep kernels ----------------
__global__ void k_norm_embed(const float* __restrict__ emb) {
    int v = blockIdx.x, d = threadIdx.x;
    float x = emb[v*D_ + d];
    float ss = blockReduceSum(x*x);
    float inv = 1.0f / fmaxf(sqrtf(ss), 1e-12f);
    float e = x * inv;
    g_en[v*D_ + d] = e;
    __half hi, lo;
    hsplit(e, hi, lo);
    int kt = d >> 5, pos = d & 31;
    g_enh[v*512 + kt*64 + pos] = hi;
    g_enh[v*512 + kt*64 + 32 + pos] = lo;
    if (d == 0) g_counts[v] = 0.f;
    if (v == 0 && d == 0) g_loss = 0.0;
}

__global__ void k_scatter_z(const float* __restrict__ z, const int* __restrict__ chans) {
    int row = blockIdx.x;
    int d = threadIdx.x;
    int b = row >> 10, n = row & 1023;
    float x = z[row*D_ + d];
    float ss = blockReduceSum(x*x);
    float inv = 1.0f / fmaxf(sqrtf(ss), 1e-12f);
    int csrc = n & 63, t = n >> 6;
    int ch = chans[b*N_ + csrc];
    int l = (b << 4) + t;
    int off = ((l << 6) + ch)*D_ + d;
    g_zl[off] = x * inv;
    g_fhat[off] = 0.f;
}

__global__ void k_transpose_w(const float* __restrict__ w) {
    int e = blockIdx.x * 256 + threadIdx.x;
    int o = e / 768, rem = e % 768;
    int i = rem / 3, k = rem % 3;
    g_Bt[i*768 + o*3 + k] = w[e];
}

// E = en(8192x256) @ Bt(256x768)
__global__ __launch_bounds__(256) void k_gemm_E() {
    __shared__ float As[32][68];
    __shared__ float Bs[32][68];
    int tid = threadIdx.x, tx = tid & 15, ty = tid >> 4;
    int rb = blockIdx.x * 64, cb = blockIdx.y * 64;
    float acc[4][4];
    #pragma unroll
    for (int i = 0; i < 4; i++)
        #pragma unroll
        for (int j = 0; j < 4; j++) acc[i][j] = 0.f;
    for (int kt = 0; kt < D_/32; kt++) {
        #pragma unroll
        for (int i = 0; i < 2; i++) {
            int f4 = tid + i*256;
            int r = f4 >> 3, kq = (f4 & 7) * 4;
            float4 v = *(const float4*)&g_en[(rb + r)*D_ + kt*32 + kq];
            As[kq+0][r] = v.x; As[kq+1][r] = v.y; As[kq+2][r] = v.z; As[kq+3][r] = v.w;
        }
        #pragma unroll
        for (int i = 0; i < 2; i++) {
            int f4 = tid + i*256;
            int r = f4 >> 4, cq = (f4 & 15) * 4;
            float4 v = *(const float4*)&g_Bt[(kt*32 + r)*768 + cb + cq];
            *(float4*)&Bs[r][cq] = v;
        }
        __syncthreads();
        #pragma unroll
        for (int kk = 0; kk < 32; kk++) {
            float4 a = *(const float4*)&As[kk][ty*4];
            float4 b = *(const float4*)&Bs[kk][tx*4];
            float ar[4] = {a.x, a.y, a.z, a.w};
            float br[4] = {b.x, b.y, b.z, b.w};
            #pragma unroll
            for (int i = 0; i < 4; i++)
                #pragma unroll
                for (int j = 0; j < 4; j++) acc[i][j] += ar[i] * br[j];
        }
        __syncthreads();
    }
    #pragma unroll
    for (int i = 0; i < 4; i++)
        #pragma unroll
        for (int j = 0; j < 4; j++)
            g_E[(rb + ty*4 + i)*768 + cb + tx*4 + j] = acc[i][j];
}

// block means of residual, L2-normalized, fp16-split (round-1 only; fhat=0)
__global__ void k_meansQ(int g) {
    int row = blockIdx.x;
    int d = threadIdx.x;
    int l = row / g, j = row % g;
    int s = C_ / g;
    int base = (l*C_ + j*s)*D_ + d;
    float sum = 0.f;
    for (int c = 0; c < s; c++) sum += g_zl[base + c*D_] - g_fhat[base + c*D_];
    sum *= (1.0f / s);
    float ss = blockReduceSum(sum*sum);
    float inv = 1.0f / fmaxf(sqrtf(ss), 1e-12f);
    sum *= inv;
    __half hi, lo;
    hsplit(sum, hi, lo);
    int kt = d >> 5, pos = d & 31;
    g_qh[(size_t)row*512 + kt*64 + pos] = hi;
    g_qh[(size_t)row*512 + kt*64 + 32 + pos] = lo;
    if (d == 0) g_keys[row] = 0ULL;
}

// ---------------- scaled fp16-split mma.sync fused GEMM + argmax ----------------
// BM=128, BN=128/pass, BK=32; 512 thr, 16 warps (4M x 4N), warp tile 32x32.
// Two fp32 accumulators: accH (hi*hi) and accM (lo'*hi + hi*lo', scale 2048).
// Smem stage = A tile + B tile (each 128 rows x 128B [hi32|lo32]) = 32KB; 4 stages.
#define NSTAGE  4
#define TILE_B  16384
#define STAGE_B (2*TILE_B)
#define QSMEM   (NSTAGE*STAGE_B)   // 131072

__device__ __forceinline__ void q_load_stage(uint32_t sb, int slot,
        const __half* Abase, const __half* Bbase, int pass, int kt, int tid) {
    int tile = tid >> 8;                 // 0=A, 1=B  (256 threads each)
    int idx = tid & 255;
    int r = idx >> 1, half = idx & 1;    // 2 threads per 128B row
    const char* g = (tile == 0)
        ? (const char*)(Abase + (size_t)r*512) + kt*128
        : (const char*)(Bbase + (size_t)(pass*128 + r)*512) + kt*128;
    uint32_t rowb = sb + (uint32_t)slot*STAGE_B + (uint32_t)tile*TILE_B + (uint32_t)r*128;
    #pragma unroll
    for (int j = 0; j < 4; j++) {
        int c = half*4 + j;
        cp16(rowb + (uint32_t)((c ^ (r & 7)) << 4), g + c*16);
    }
}

__global__ __launch_bounds__(512, 1) void k_qmma(int Vper) {
    extern __shared__ float smf[];
    uint32_t sb = smem_u32(smf);
    int tid = threadIdx.x;
    int lane = tid & 31, wid = tid >> 5;
    int quad = lane >> 2, tq = lane & 3;
    int mbase = (wid >> 2) * 32;         // warp_m in {0..3}
    int nbase = (wid & 3) * 32;          // warp_n in {0..3}
    int rowbase = blockIdx.x * 128;
    int ctaV = blockIdx.y * Vper;
    int npass = Vper >> 7;
    int niter = npass * 8;

    const __half* Abase = g_qh + (size_t)rowbase * 512;
    const __half* Bbase = g_enh + (size_t)ctaV * 512;

    // ldmatrix address components
    int l7 = lane & 7;
    int l16 = (lane >> 4) & 1;
    int bl3 = (lane >> 3) & 1;
    uint32_t aRow[2], bRow[2];
    #pragma unroll
    for (int mt = 0; mt < 2; mt++)
        aRow[mt] = (uint32_t)(mbase + mt*16 + (lane & 15)) * 128u;
    #pragma unroll
    for (int np = 0; np < 2; np++)
        bRow[np] = (uint32_t)(nbase + np*16 + l16*8 + l7) * 128u;

    float accH[2][4][4], accM[2][4][4];
    float bv[4]; int bi[4];
    #pragma unroll
    for (int i = 0; i < 4; i++) { bv[i] = -1e30f; bi[i] = 0; }

    // prologue: fill 3 stages (prefetch distance 3)
    q_load_stage(sb, 0, Abase, Bbase, 0, 0, tid); CP_COMMIT();
    q_load_stage(sb, 1, Abase, Bbase, 0, 1, tid); CP_COMMIT();
    q_load_stage(sb, 2, Abase, Bbase, 0, 2, tid); CP_COMMIT();

    int s = 0;
    for (int it = 0; it < niter; it++) {
        int pass = it >> 3, kt = it & 7;

        asm volatile("cp.async.wait_group 2;" ::: "memory");
        __syncthreads();

        int ld = it + 3;
        if (ld < niter) {
            int s2 = s + 3; if (s2 >= NSTAGE) s2 -= NSTAGE;
            q_load_stage(sb, s2, Abase, Bbase, ld >> 3, ld & 7, tid);
        }
        CP_COMMIT();

        if (kt == 0) {
            #pragma unroll
            for (int mt = 0; mt < 2; mt++)
                #pragma unroll
                for (int nt = 0; nt < 4; nt++)
                    #pragma unroll
                    for (int rg = 0; rg < 4; rg++) { accH[mt][nt][rg] = 0.f; accM[mt][nt][rg] = 0.f; }
        }

        uint32_t tA = sb + (uint32_t)s*STAGE_B;
        uint32_t tB = tA + TILE_B;
        #pragma unroll
        for (int kg = 0; kg < 2; kg++) {
            uint32_t ah[2][4], al[2][4];
            int chA = (kg << 1) + l16;
            #pragma unroll
            for (int mt = 0; mt < 2; mt++) {
                ldsm4(ah[mt], tA + aRow[mt] + (uint32_t)((chA ^ l7) << 4));
                ldsm4(al[mt], tA + aRow[mt] + (uint32_t)(((chA + 4) ^ l7) << 4));
            }
            int chB = (kg << 1) + bl3;
            #pragma unroll
            for (int np = 0; np < 2; np++) {
                uint32_t bh_[4], bl_[4];
                ldsm4(bh_, tB + bRow[np] + (uint32_t)((chB ^ l7) << 4));
                ldsm4(bl_, tB + bRow[np] + (uint32_t)(((chB + 4) ^ l7) << 4));
                // dependency-spaced issue: all accH first, then the two accM
                // terms split across mt so same-accumulator mmas are >=2 apart.
                #pragma unroll
                for (int h = 0; h < 2; h++) {
                    int nt = np*2 + h;
                    #pragma unroll
                    for (int mt = 0; mt < 2; mt++)
                        mma16(accH[mt][nt], ah[mt], bh_ + h*2);
                    #pragma unroll
                    for (int mt = 0; mt < 2; mt++)
                        mma16(accM[mt][nt], al[mt], bh_ + h*2);
                    #pragma unroll
                    for (int mt = 0; mt < 2; mt++)
                        mma16(accM[mt][nt], ah[mt], bl_ + h*2);
                }
            }
        }

        if (kt == 7) {
            int vb = ctaV + pass*128 + nbase;
            #pragma unroll
            for (int mt = 0; mt < 2; mt++) {
                #pragma unroll
                for (int nt = 0; nt < 4; nt++) {
                    int c0 = vb + nt*8 + tq*2;
                    float v0 = accH[mt][nt][0] + accM[mt][nt][0]*LO_INV;
                    float v1 = accH[mt][nt][1] + accM[mt][nt][1]*LO_INV;
                    float v2 = accH[mt][nt][2] + accM[mt][nt][2]*LO_INV;
                    float v3 = accH[mt][nt][3] + accM[mt][nt][3]*LO_INV;
                    int slo = mt*2, shi = mt*2 + 1;
                    if (v0 > bv[slo]) { bv[slo] = v0; bi[slo] = c0; }
                    if (v1 > bv[slo]) { bv[slo] = v1; bi[slo] = c0 + 1; }
                    if (v2 > bv[shi]) { bv[shi] = v2; bi[shi] = c0; }
                    if (v3 > bv[shi]) { bv[shi] = v3; bi[shi] = c0 + 1; }
                }
            }
        }
        s++; if (s == NSTAGE) s = 0;
    }

    // reduce across the 4 lanes of each quad-group, then atomicMax per row
    #pragma unroll
    for (int slot = 0; slot < 4; slot++) {
        float v = bv[slot]; int i = bi[slot];
        #pragma unroll
        for (int off = 1; off < 4; off <<= 1) {
            float v2 = __shfl_xor_sync(0xffffffffu, v, off);
            int   i2 = __shfl_xor_sync(0xffffffffu, i, off);
            if (v2 > v || (v2 == v && i2 < i)) { v = v2; i = i2; }
        }
        if (tq == 0) {
            int mt = slot >> 1;
            int row = rowbase + mbase + mt*16 + quad + ((slot & 1) ? 8 : 0);
            ull key = ((ull)order_f(v) << 32) | (ull)(0xFFFFFFFFu - (unsigned)i);
            atomicMax(&g_keys[row], key);
        }
    }
}

// ---------------- fused finalize + assemble + next-round means ----------------
// One block per l. Decodes argmax keys, writes idx output + counts, applies
// the gathered phi conv, updates f_hat + loss, and (if g_next>0) emits the
// next round's fp16-split queries without re-reading zl/fhat from HBM.
__global__ void k_post(int g, int colbase, int g_next,
                       const float* __restrict__ phib, float* __restrict__ out) {
    int l = blockIdx.x, d = threadIdx.x;
    int s = C_ / g;
    __shared__ int sidx[64];
    if (d < g) {
        ull key = g_keys[l*g + d];
        int idx = (int)(0xFFFFFFFFu - (unsigned)(key & 0xFFFFFFFFu));
        sidx[d] = idx;
        out[OFF_IDX + l*85 + colbase + d] = (float)idx;
        atomicAdd(&g_counts[idx], 1.0f);
    }
    __syncthreads();
    float bb = phib[d];
    float lsum = 0.f;
    int sn = g_next ? (C_ / g_next) : C_;
    float msum = 0.f;
    for (int c = 0; c < C_; c++) {
        int vb = sidx[c / s];
        float y = g_E[vb*768 + d*3 + 1] + bb;
        if (c > 0)      y += g_E[sidx[(c-1)/s]*768 + d*3 + 0];
        if (c < C_-1)   y += g_E[sidx[(c+1)/s]*768 + d*3 + 2];
        float h = 0.5f*g_en[vb*D_ + d] + 0.5f*y;
        int off = (l*C_ + c)*D_ + d;
        float f = g_fhat[off] + h;
        g_fhat[off] = f;
        float zv = g_zl[off];
        float diff = f - zv;
        lsum += diff * diff;
        msum += (zv - f);
        if (g_next && ((c + 1) % sn == 0)) {
            float m = msum * (1.0f / sn);
            float ss = blockReduceSum(m*m);
            float invn = 1.0f / fmaxf(sqrtf(ss), 1e-12f);
            m *= invn;
            __half hi, lo;
            hsplit(m, hi, lo);
            int row = l*g_next + (c / sn);
            int kt = d >> 5, pos = d & 31;
            g_qh[(size_t)row*512 + kt*64 + pos] = hi;
            g_qh[(size_t)row*512 + kt*64 + 32 + pos] = lo;
            if (d == 0) g_keys[row] = 0ULL;
            msum = 0.f;
        }
    }
    float tot = blockReduceSum(lsum);
    if (d == 0) atomicAdd(&g_loss, (double)tot);
}

__global__ void k_gather_zq(const int* __restrict__ chans, float* __restrict__ out) {
    int row = blockIdx.x;
    int d = threadIdx.x;
    int b = row >> 10, n = row & 1023;
    int csrc = n & 63, t = n >> 6;
    int ch = chans[b*N_ + csrc];
    int l = (b << 4) + t;
    out[row*D_ + d] = g_fhat[((l << 6) + ch)*D_ + d];
}

__global__ void k_tail(const float* __restrict__ cs, float* __restrict__ out) {
    int v = blockIdx.x * 256 + threadIdx.x;
    out[OFF_CS + v] = 0.99f * cs[v] + 0.01f * g_counts[v];
    if (v == 0)
        out[OFF_LOSS] = (float)(g_loss * (1.25 / (4.0 * (double)(L_*C_*D_))));
}

// ---------------- launch ----------------
extern "C" void kernel_launch(void* const* d_in, const int* in_sizes, int n_in,
                              void* d_out, int out_size) {
    const float* z     = (const float*)d_in[0];
    const int*   chans = (const int*)d_in[1];
    const float* emb   = (const float*)d_in[3];
    const float* w     = (const float*)d_in[4];
    const float* phib  = (const float*)d_in[5];
    const float* cs    = (const float*)d_in[6];
    float* out = (float*)d_out;

    cudaFuncSetAttribute(k_qmma, cudaFuncAttributeMaxDynamicSharedMemorySize, QSMEM);

    const int gs[4]      = {1, 4, 16, 64};
    const int colbase[4] = {0, 1, 5, 21};
    const int gnext[4]   = {4, 16, 64, 0};
    // CTA counts (BM=128): 256 / 256 / 128 / 1024
    const int vsplit[4]  = {16, 4, 1, 2};

    // Launch order puts the first k_qmma at launch #4 (ncu capture slot).
    k_norm_embed<<<V_, 256>>>(emb);                            // #1
    k_scatter_z<<<B_*N_, 256>>>(z, chans);                     // #2
    k_meansQ<<<L_, 256>>>(1);                                  // #3
    k_qmma<<<dim3(L_/128, vsplit[0]), 512, QSMEM>>>(V_/vsplit[0]); // #4
    k_transpose_w<<<768, 256>>>(w);                            // #5
    k_gemm_E<<<dim3(V_/64, 12), 256>>>();                      // #6
    k_post<<<L_, 256>>>(1, colbase[0], gnext[0], phib, out);

    for (int r = 1; r < 4; r++) {
        int g = gs[r];
        int M = L_ * g;
        k_qmma<<<dim3(M/128, vsplit[r]), 512, QSMEM>>>(V_ / vsplit[r]);
        k_post<<<L_, 256>>>(g, colbase[r], gnext[r], phib, out);
    }

    k_gather_zq<<<B_*N_, 256>>>(chans, out);
    k_tail<<<V_/256, 256>>>(cs, out);
}

// round 17
// speedup vs baseline: 1.5878x; 1.2242x over previous
#include <cuda_runtime.h>
#include <cuda_fp16.h>
#include <cstdint>

// ---------------- problem constants ----------------
#define D_   256
#define V_   8192
#define B_   64
#define T_   16
#define L_   1024          // B*T
#define C_   64            // C_STD
#define N_   1024          // T*C_STD
#define ZQ_SIZE  (B_*N_*D_)            // 16777216
#define OFF_LOSS (ZQ_SIZE)
#define OFF_IDX  (ZQ_SIZE+1)
#define NIDX     (L_*85)
#define OFF_CS   (OFF_IDX + NIDX)
#define MAXM     (L_*64)               // 65536

#define LO_SCALE 2048.0f
#define LO_INV   (1.0f/2048.0f)

typedef unsigned long long ull;

// ---------------- device scratch ----------------
__device__ float g_en[V_*D_];          // normalized embedding (8 MB)
__device__ __half g_enh[V_*512];       // fp16 split codes, per k-chunk [hi32|lo32], lo scaled 2048 (8 MB)
__device__ float g_Bt[D_*768];
__device__ float g_E[V_*768];          // phi conv of codes (24 MB)
__device__ float g_zl[L_*C_*D_];       // z_LND (64 MB)
__device__ float g_fhat[L_*C_*D_];     // running f_hat (64 MB)
__device__ __half g_qh[MAXM*512];      // fp16 split queries (64 MB)
__device__ ull   g_keys[MAXM];
__device__ float g_counts[V_];
__device__ double g_loss;

// ---------------- helpers ----------------
__device__ __forceinline__ float blockReduceSum(float v) {
    __shared__ float sh[8];
    int lane = threadIdx.x & 31, w = threadIdx.x >> 5;
    #pragma unroll
    for (int o = 16; o; o >>= 1) v += __shfl_down_sync(0xffffffffu, v, o);
    if (lane == 0) sh[w] = v;
    __syncthreads();
    if (w == 0) {
        v = (lane < 8) ? sh[lane] : 0.f;
        #pragma unroll
        for (int o = 4; o; o >>= 1) v += __shfl_down_sync(0xffffffffu, v, o);
        if (lane == 0) sh[0] = v;
    }
    __syncthreads();
    return sh[0];
}

__device__ __forceinline__ unsigned order_f(float f) {
    unsigned u = __float_as_uint(f);
    return (u & 0x80000000u) ? ~u : (u | 0x80000000u);
}

__device__ __forceinline__ uint32_t smem_u32(const void* p) {
    uint32_t a;
    asm("{ .reg .u64 t; cvta.to.shared.u64 t, %1; cvt.u32.u64 %0, t; }" : "=r"(a) : "l"(p));
    return a;
}

__device__ __forceinline__ void cp16(uint32_t saddr, const void* g) {
    asm volatile("cp.async.cg.shared.global [%0], [%1], 16;" :: "r"(saddr), "l"(g) : "memory");
}
#define CP_COMMIT() asm volatile("cp.async.commit_group;" ::: "memory")

__device__ __forceinline__ void mma16(float* d, const uint32_t* a, const uint32_t* b) {
    asm("mma.sync.aligned.m16n8k16.row.col.f32.f16.f16.f32 "
        "{%0,%1,%2,%3}, {%4,%5,%6,%7}, {%8,%9}, {%0,%1,%2,%3};"
        : "+f"(d[0]), "+f"(d[1]), "+f"(d[2]), "+f"(d[3])
        : "r"(a[0]), "r"(a[1]), "r"(a[2]), "r"(a[3]), "r"(b[0]), "r"(b[1]));
}

__device__ __forceinline__ void ldsm4(uint32_t* r, uint32_t addr) {
    asm volatile("ldmatrix.sync.aligned.m8n8.x4.shared.b16 {%0,%1,%2,%3}, [%4];"
        : "=r"(r[0]), "=r"(r[1]), "=r"(r[2]), "=r"(r[3]) : "r"(addr));
}

// fp16 split with scaled low word: x ~= hi + lo/2048, lo stays fp16-normal
__device__ __forceinline__ void hsplit(float x, __half& hi, __half& lo) {
    hi = __float2half_rn(x);
    lo = __float2half_rn((x - __half2float(hi)) * LO_SCALE);
}

// ---------------- prep kernels ----------------
__global__ void k_norm_embed(const float* __restrict__ emb) {
    int v = blockIdx.x, d = threadIdx.x;
    float x = emb[v*D_ + d];
    float ss = blockReduceSum(x*x);
    float inv = 1.0f / fmaxf(sqrtf(ss), 1e-12f);
    float e = x * inv;
    g_en[v*D_ + d] = e;
    __half hi, lo;
    hsplit(e, hi, lo);
    int kt = d >> 5, pos = d & 31;
    g_enh[v*512 + kt*64 + pos] = hi;
    g_enh[v*512 + kt*64 + 32 + pos] = lo;
    if (d == 0) g_counts[v] = 0.f;
    if (v == 0 && d == 0) g_loss = 0.0;
}

__global__ void k_scatter_z(const float* __restrict__ z, const int* __restrict__ chans) {
    int row = blockIdx.x;
    int d = threadIdx.x;
    int b = row >> 10, n = row & 1023;
    float x = z[row*D_ + d];
    float ss = blockReduceSum(x*x);
    float inv = 1.0f / fmaxf(sqrtf(ss), 1e-12f);
    int csrc = n & 63, t = n >> 6;
    int ch = chans[b*N_ + csrc];
    int l = (b << 4) + t;
    int off = ((l << 6) + ch)*D_ + d;
    g_zl[off] = x * inv;
    g_fhat[off] = 0.f;
}

__global__ void k_transpose_w(const float* __restrict__ w) {
    int e = blockIdx.x * 256 + threadIdx.x;
    int o = e / 768, rem = e % 768;
    int i = rem / 3, k = rem % 3;
    g_Bt[i*768 + o*3 + k] = w[e];
}

// E = en(8192x256) @ Bt(256x768)
__global__ __launch_bounds__(256) void k_gemm_E() {
    __shared__ float As[32][68];
    __shared__ float Bs[32][68];
    int tid = threadIdx.x, tx = tid & 15, ty = tid >> 4;
    int rb = blockIdx.x * 64, cb = blockIdx.y * 64;
    float acc[4][4];
    #pragma unroll
    for (int i = 0; i < 4; i++)
        #pragma unroll
        for (int j = 0; j < 4; j++) acc[i][j] = 0.f;
    for (int kt = 0; kt < D_/32; kt++) {
        #pragma unroll
        for (int i = 0; i < 2; i++) {
            int f4 = tid + i*256;
            int r = f4 >> 3, kq = (f4 & 7) * 4;
            float4 v = *(const float4*)&g_en[(rb + r)*D_ + kt*32 + kq];
            As[kq+0][r] = v.x; As[kq+1][r] = v.y; As[kq+2][r] = v.z; As[kq+3][r] = v.w;
        }
        #pragma unroll
        for (int i = 0; i < 2; i++) {
            int f4 = tid + i*256;
            int r = f4 >> 4, cq = (f4 & 15) * 4;
            float4 v = *(const float4*)&g_Bt[(kt*32 + r)*768 + cb + cq];
            *(float4*)&Bs[r][cq] = v;
        }
        __syncthreads();
        #pragma unroll
        for (int kk = 0; kk < 32; kk++) {
            float4 a = *(const float4*)&As[kk][ty*4];
            float4 b = *(const float4*)&Bs[kk][tx*4];
            float ar[4] = {a.x, a.y, a.z, a.w};
            float br[4] = {b.x, b.y, b.z, b.w};
            #pragma unroll
            for (int i = 0; i < 4; i++)
                #pragma unroll
                for (int j = 0; j < 4; j++) acc[i][j] += ar[i] * br[j];
        }
        __syncthreads();
    }
    #pragma unroll
    for (int i = 0; i < 4; i++)
        #pragma unroll
        for (int j = 0; j < 4; j++)
            g_E[(rb + ty*4 + i)*768 + cb + tx*4 + j] = acc[i][j];
}

// round-1 queries: block means of zl (fhat==0), L2-normalized, fp16-split
__global__ void k_meansQ1() {
    int row = blockIdx.x;                // row = l
    int d = threadIdx.x;
    int base = row*C_*D_ + d;
    float sum = 0.f;
    for (int c = 0; c < C_; c++) sum += g_zl[base + c*D_];
    sum *= (1.0f / C_);
    float ss = blockReduceSum(sum*sum);
    float inv = 1.0f / fmaxf(sqrtf(ss), 1e-12f);
    sum *= inv;
    __half hi, lo;
    hsplit(sum, hi, lo);
    int kt = d >> 5, pos = d & 31;
    g_qh[(size_t)row*512 + kt*64 + pos] = hi;
    g_qh[(size_t)row*512 + kt*64 + 32 + pos] = lo;
    if (d == 0) g_keys[row] = 0ULL;
}

// ---------------- scaled fp16-split mma.sync fused GEMM + argmax ----------------
// BM=128, BN=128/pass, BK=32; 512 thr, 16 warps (4M x 4N), warp tile 32x32.
// A (all 8 K-chunks, 128 KB) persistent in smem; B streamed, 4 stages x 16 KB.
#define NSTAGE  4
#define TILE_B  16384
#define A_BYTES (8*TILE_B)             // 131072
#define QSMEM   (A_BYTES + NSTAGE*TILE_B)   // 196608

__device__ __forceinline__ void load_A_chunk(uint32_t sb, int kt,
        const __half* Abase, int tid) {
    #pragma unroll
    for (int rep = 0; rep < 2; rep++) {
        int i = tid + rep*512;
        int r = i >> 3, c = i & 7;
        const char* g = (const char*)(Abase + (size_t)r*512) + kt*128 + c*16;
        uint32_t rowb = sb + (uint32_t)kt*TILE_B + (uint32_t)r*128;
        cp16(rowb + (uint32_t)((c ^ (r & 7)) << 4), g);
    }
}

__device__ __forceinline__ void load_B_stage(uint32_t sb, int slot,
        const __half* Bbase, int pass, int kt, int tid) {
    #pragma unroll
    for (int rep = 0; rep < 2; rep++) {
        int i = tid + rep*512;
        int r = i >> 3, c = i & 7;
        const char* g = (const char*)(Bbase + (size_t)(pass*128 + r)*512) + kt*128 + c*16;
        uint32_t rowb = sb + A_BYTES + (uint32_t)slot*TILE_B + (uint32_t)r*128;
        cp16(rowb + (uint32_t)((c ^ (r & 7)) << 4), g);
    }
}

__global__ __launch_bounds__(512, 1) void k_qmma(int Vper) {
    extern __shared__ float smf[];
    uint32_t sb = smem_u32(smf);
    int tid = threadIdx.x;
    int lane = tid & 31, wid = tid >> 5;
    int quad = lane >> 2, tq = lane & 3;
    int mbase = (wid >> 2) * 32;         // warp_m in {0..3}
    int nbase = (wid & 3) * 32;          // warp_n in {0..3}
    int rowbase = blockIdx.x * 128;
    int ctaV = blockIdx.y * Vper;
    int npass = Vper >> 7;
    int niter = npass * 8;

    const __half* Abase = g_qh + (size_t)rowbase * 512;
    const __half* Bbase = g_enh + (size_t)ctaV * 512;

    // ldmatrix address components
    int l7 = lane & 7;
    int l16 = (lane >> 4) & 1;
    int bl3 = (lane >> 3) & 1;
    uint32_t aRow[2], bRow[2];
    #pragma unroll
    for (int mt = 0; mt < 2; mt++)
        aRow[mt] = (uint32_t)(mbase + mt*16 + (lane & 15)) * 128u;
    #pragma unroll
    for (int np = 0; np < 2; np++)
        bRow[np] = (uint32_t)(nbase + np*16 + l16*8 + l7) * 128u;

    float accH[2][4][4], accM[2][4][4];
    float bv[4]; int bi[4];
    #pragma unroll
    for (int i = 0; i < 4; i++) { bv[i] = -1e30f; bi[i] = 0; }

    // prologue: A (all chunks, one group) then 3 B stages (distance 3)
    #pragma unroll
    for (int kt = 0; kt < 8; kt++) load_A_chunk(sb, kt, Abase, tid);
    CP_COMMIT();
    load_B_stage(sb, 0, Bbase, 0, 0, tid); CP_COMMIT();
    load_B_stage(sb, 1, Bbase, 0, 1, tid); CP_COMMIT();
    load_B_stage(sb, 2, Bbase, 0, 2, tid); CP_COMMIT();

    int s = 0;
    for (int it = 0; it < niter; it++) {
        int pass = it >> 3, kt = it & 7;

        asm volatile("cp.async.wait_group 2;" ::: "memory");
        __syncthreads();

        int ld = it + 3;
        if (ld < niter) {
            int s2 = s + 3; if (s2 >= NSTAGE) s2 -= NSTAGE;
            load_B_stage(sb, s2, Bbase, ld >> 3, ld & 7, tid);
        }
        CP_COMMIT();

        if (kt == 0) {
            #pragma unroll
            for (int mt = 0; mt < 2; mt++)
                #pragma unroll
                for (int nt = 0; nt < 4; nt++)
                    #pragma unroll
                    for (int rg = 0; rg < 4; rg++) { accH[mt][nt][rg] = 0.f; accM[mt][nt][rg] = 0.f; }
        }

        uint32_t tA = sb + (uint32_t)kt*TILE_B;       // persistent A chunk
        uint32_t tB = sb + A_BYTES + (uint32_t)s*TILE_B;
        #pragma unroll
        for (int kg = 0; kg < 2; kg++) {
            uint32_t ah[2][4], al[2][4];
            int chA = (kg << 1) + l16;
            #pragma unroll
            for (int mt = 0; mt < 2; mt++) {
                ldsm4(ah[mt], tA + aRow[mt] + (uint32_t)((chA ^ l7) << 4));
                ldsm4(al[mt], tA + aRow[mt] + (uint32_t)(((chA + 4) ^ l7) << 4));
            }
            int chB = (kg << 1) + bl3;
            #pragma unroll
            for (int np = 0; np < 2; np++) {
                uint32_t bh_[4], bl_[4];
                ldsm4(bh_, tB + bRow[np] + (uint32_t)((chB ^ l7) << 4));
                ldsm4(bl_, tB + bRow[np] + (uint32_t)(((chB + 4) ^ l7) << 4));
                #pragma unroll
                for (int h = 0; h < 2; h++) {
                    int nt = np*2 + h;
                    #pragma unroll
                    for (int mt = 0; mt < 2; mt++)
                        mma16(accH[mt][nt], ah[mt], bh_ + h*2);
                    #pragma unroll
                    for (int mt = 0; mt < 2; mt++)
                        mma16(accM[mt][nt], al[mt], bh_ + h*2);
                    #pragma unroll
                    for (int mt = 0; mt < 2; mt++)
                        mma16(accM[mt][nt], ah[mt], bl_ + h*2);
                }
            }
        }

        if (kt == 7) {
            int vb = ctaV + pass*128 + nbase;
            #pragma unroll
            for (int mt = 0; mt < 2; mt++) {
                #pragma unroll
                for (int nt = 0; nt < 4; nt++) {
                    int c0 = vb + nt*8 + tq*2;
                    float v0 = accH[mt][nt][0] + accM[mt][nt][0]*LO_INV;
                    float v1 = accH[mt][nt][1] + accM[mt][nt][1]*LO_INV;
                    float v2 = accH[mt][nt][2] + accM[mt][nt][2]*LO_INV;
                    float v3 = accH[mt][nt][3] + accM[mt][nt][3]*LO_INV;
                    int slo = mt*2, shi = mt*2 + 1;
                    if (v0 > bv[slo]) { bv[slo] = v0; bi[slo] = c0; }
                    if (v1 > bv[slo]) { bv[slo] = v1; bi[slo] = c0 + 1; }
                    if (v2 > bv[shi]) { bv[shi] = v2; bi[shi] = c0; }
                    if (v3 > bv[shi]) { bv[shi] = v3; bi[shi] = c0 + 1; }
                }
            }
        }
        s++; if (s == NSTAGE) s = 0;
    }

    // reduce across the 4 lanes of each quad-group, then atomicMax per row
    #pragma unroll
    for (int slot = 0; slot < 4; slot++) {
        float v = bv[slot]; int i = bi[slot];
        #pragma unroll
        for (int off = 1; off < 4; off <<= 1) {
            float v2 = __shfl_xor_sync(0xffffffffu, v, off);
            int   i2 = __shfl_xor_sync(0xffffffffu, i, off);
            if (v2 > v || (v2 == v && i2 < i)) { v = v2; i = i2; }
        }
        if (tq == 0) {
            int mt = slot >> 1;
            int row = rowbase + mbase + mt*16 + quad + ((slot & 1) ? 8 : 0);
            ull key = ((ull)order_f(v) << 32) | (ull)(0xFFFFFFFFu - (unsigned)i);
            atomicMax(&g_keys[row], key);
        }
    }
}

// ---------------- fused finalize + assemble + next-round means ----------------
__global__ void k_post(int g, int colbase, int g_next,
                       const float* __restrict__ phib, float* __restrict__ out) {
    int l = blockIdx.x, d = threadIdx.x;
    int s = C_ / g;
    __shared__ int sidx[64];
    if (d < g) {
        ull key = g_keys[l*g + d];
        int idx = (int)(0xFFFFFFFFu - (unsigned)(key & 0xFFFFFFFFu));
        sidx[d] = idx;
        out[OFF_IDX + l*85 + colbase + d] = (float)idx;
        atomicAdd(&g_counts[idx], 1.0f);
    }
    __syncthreads();
    float bb = phib[d];
    float lsum = 0.f;
    int sn = g_next ? (C_ / g_next) : C_;
    float msum = 0.f;
    for (int c = 0; c < C_; c++) {
        int vb = sidx[c / s];
        float y = g_E[vb*768 + d*3 + 1] + bb;
        if (c > 0)      y += g_E[sidx[(c-1)/s]*768 + d*3 + 0];
        if (c < C_-1)   y += g_E[sidx[(c+1)/s]*768 + d*3 + 2];
        float h = 0.5f*g_en[vb*D_ + d] + 0.5f*y;
        int off = (l*C_ + c)*D_ + d;
        float f = g_fhat[off] + h;
        g_fhat[off] = f;
        float zv = g_zl[off];
        float diff = f - zv;
        lsum += diff * diff;
        msum += (zv - f);
        if (g_next && ((c + 1) % sn == 0)) {
            float m = msum * (1.0f / sn);
            float ss = blockReduceSum(m*m);
            float invn = 1.0f / fmaxf(sqrtf(ss), 1e-12f);
            m *= invn;
            __half hi, lo;
            hsplit(m, hi, lo);
            int row = l*g_next + (c / sn);
            int kt = d >> 5, pos = d & 31;
            g_qh[(size_t)row*512 + kt*64 + pos] = hi;
            g_qh[(size_t)row*512 + kt*64 + 32 + pos] = lo;
            if (d == 0) g_keys[row] = 0ULL;
            msum = 0.f;
        }
    }
    float tot = blockReduceSum(lsum);
    if (d == 0) atomicAdd(&g_loss, (double)tot);
}

__global__ void k_gather_zq(const int* __restrict__ chans, float* __restrict__ out) {
    int row = blockIdx.x;
    int d = threadIdx.x;
    int b = row >> 10, n = row & 1023;
    int csrc = n & 63, t = n >> 6;
    int ch = chans[b*N_ + csrc];
    int l = (b << 4) + t;
    out[row*D_ + d] = g_fhat[((l << 6) + ch)*D_ + d];
}

__global__ void k_tail(const float* __restrict__ cs, float* __restrict__ out) {
    int v = blockIdx.x * 256 + threadIdx.x;
    out[OFF_CS + v] = 0.99f * cs[v] + 0.01f * g_counts[v];
    if (v == 0)
        out[OFF_LOSS] = (float)(g_loss * (1.25 / (4.0 * (double)(L_*C_*D_))));
}

// ---------------- launch ----------------
extern "C" void kernel_launch(void* const* d_in, const int* in_sizes, int n_in,
                              void* d_out, int out_size) {
    const float* z     = (const float*)d_in[0];
    const int*   chans = (const int*)d_in[1];
    const float* emb   = (const float*)d_in[3];
    const float* w     = (const float*)d_in[4];
    const float* phib  = (const float*)d_in[5];
    const float* cs    = (const float*)d_in[6];
    float* out = (float*)d_out;

    cudaFuncSetAttribute(k_qmma, cudaFuncAttributeMaxDynamicSharedMemorySize, QSMEM);

    const int gs[4]      = {1, 4, 16, 64};
    const int colbase[4] = {0, 1, 5, 21};
    const int gnext[4]   = {4, 16, 64, 0};
    // CTA counts (BM=128): 256 / 256 / 128 / 1024
    const int vsplit[4]  = {16, 4, 1, 2};

    // Launch order puts the first k_qmma at launch #4 (ncu capture slot).
    k_norm_embed<<<V_, 256>>>(emb);                            // #1
    k_scatter_z<<<B_*N_, 256>>>(z, chans);                     // #2
    k_meansQ1<<<L_, 256>>>();                                  // #3
    k_qmma<<<dim3(L_/128, vsplit[0]), 512, QSMEM>>>(V_/vsplit[0]); // #4
    k_transpose_w<<<768, 256>>>(w);                            // #5
    k_gemm_E<<<dim3(V_/64, 12), 256>>>();                      // #6
    k_post<<<L_, 256>>>(1, colbase[0], gnext[0], phib, out);

    for (int r = 1; r < 4; r++) {
        int g = gs[r];
        int M = L_ * g;
        k_qmma<<<dim3(M/128, vsplit[r]), 512, QSMEM>>>(V_ / vsplit[r]);
        k_post<<<L_, 256>>>(g, colbase[r], gnext[r], phib, out);
    }

    k_gather_zq<<<B_*N_, 256>>>(chans, out);
    k_tail<<<V_/256, 256>>>(cs, out);
}